// round 3
// baseline (speedup 1.0000x reference)
#include <cuda_runtime.h>
#include <cuda_bf16.h>
#include <cstdint>
#include <math.h>

#define B_    32
#define T_    512
#define D_    300
#define U_    300
#define NG_   1200       // 4*U
#define ZPAD  1216       // padded zx row stride
#define M_    16384      // B*T

// recurrence tiling
#define NU    20         // units per CTA (15 CTAs * 20 = 300 exact)
#define NCOL  80         // 4*NU gate columns per CTA
#define NCP   40         // column pairs
#define KCH   10         // k chunks
#define KC    30         // k per chunk (10*30 = 300)
#define BG    8          // batches per CTA (4 groups * 8 = 32)
#define UGN   15         // unit-group CTAs per (dir,batch-group)
#define RTHREADS 416

// ------------------- static device scratch (no allocs allowed) -------------
__device__ __align__(16) float g_zx[2][M_][ZPAD];     // x@Wk+b per dir
__device__ __align__(16) float g_hs[2][B_][T_][U_];   // h history per dir
__device__ __align__(16) float g_h[2][2][B_][U_];     // [parity][dir][b][u]
__device__ unsigned g_sync[8][64];                    // [grp]: [0]=cnt [32]=sense

// ------------------- helpers ----------------------------------------------
union UF2 { float2 f; unsigned long long u; };
__device__ __forceinline__ unsigned long long pack2(float a, float b) {
    UF2 x; x.f = make_float2(a, b); return x.u;
}
__device__ __forceinline__ float2 unpack2(unsigned long long v) {
    UF2 x; x.u = v; return x.f;
}
__device__ __forceinline__ void ffma2(unsigned long long& d, unsigned long long a,
                                      unsigned long long b) {
    asm("fma.rn.f32x2 %0, %1, %2, %0;" : "+l"(d) : "l"(a), "l"(b));
}
__device__ __forceinline__ float sigm(float x) { return 1.f / (1.f + __expf(-x)); }

// ------------------- kernel 1: zx = gather(emb) @ Wk + b -------------------
// M=16384, N=1216(pad), K=304(pad). BM=BN=64, BK=8, 256 thr, 4x4 micro, f32x2 k-pairs.
__global__ void __launch_bounds__(256) gemm_zx(const int* __restrict__ idx,
                                               const float* __restrict__ emb,
                                               const float* __restrict__ WkF,
                                               const float* __restrict__ WkB,
                                               const float* __restrict__ bF,
                                               const float* __restrict__ bB) {
    const int dir = blockIdx.z;
    const float* __restrict__ Wk   = dir ? WkB : WkF;
    const float* __restrict__ bias = dir ? bB  : bF;
    const int m0 = blockIdx.x * 64;
    const int n0 = blockIdx.y * 64;

    __shared__ unsigned long long A_s[64][4];   // [m][k-pair]
    __shared__ float B_s[64][10];               // [n][k], padded row (40B)
    __shared__ int   row_s[64];

    const int tid = threadIdx.x;
    if (tid < 64) row_s[tid] = idx[m0 + tid];
    __syncthreads();

    unsigned long long acc[4][4];
#pragma unroll
    for (int i = 0; i < 4; i++)
#pragma unroll
        for (int j = 0; j < 4; j++) acc[i][j] = 0ULL;

    const int mt = tid >> 4;   // 0..15
    const int nt = tid & 15;   // 0..15

    for (int k0 = 0; k0 < 304; k0 += 8) {
        // A tile: m = tid/4 (0..63), kk = (tid%4)*2
        {
            int m  = tid >> 2;
            int kk = (tid & 3) * 2;
            int k  = k0 + kk;
            float vx = 0.f, vy = 0.f;
            const float* ep = emb + (size_t)row_s[m] * D_;
            if (k + 1 < D_) { float2 v = *(const float2*)(ep + k); vx = v.x; vy = v.y; }
            else if (k < D_) { vx = ep[k]; }
            A_s[m][kk >> 1] = pack2(vx, vy);
        }
        // B tile (transposed to [n][k]): k = tid/32, n = (tid%32)*2
        {
            int kk = tid >> 5;
            int nn = (tid & 31) * 2;
            int k  = k0 + kk;
            int n  = n0 + nn;
            float vx = 0.f, vy = 0.f;
            if (k < D_) {
                if (n + 1 < NG_) { float2 v = *(const float2*)(Wk + (size_t)k * NG_ + n); vx = v.x; vy = v.y; }
                else if (n < NG_) { vx = Wk[(size_t)k * NG_ + n]; }
            }
            B_s[nn][kk]     = vx;
            B_s[nn + 1][kk] = vy;
        }
        __syncthreads();
#pragma unroll
        for (int kp = 0; kp < 4; kp++) {
            unsigned long long a2[4], b2[4];
#pragma unroll
            for (int i = 0; i < 4; i++) a2[i] = A_s[mt * 4 + i][kp];
#pragma unroll
            for (int j = 0; j < 4; j++) b2[j] = *(const unsigned long long*)&B_s[nt * 4 + j][kp * 2];
#pragma unroll
            for (int i = 0; i < 4; i++)
#pragma unroll
                for (int j = 0; j < 4; j++) ffma2(acc[i][j], a2[i], b2[j]);
        }
        __syncthreads();
    }
#pragma unroll
    for (int i = 0; i < 4; i++) {
        int m = m0 + mt * 4 + i;
        float r[4];
#pragma unroll
        for (int j = 0; j < 4; j++) {
            int n = n0 + nt * 4 + j;
            float2 p = unpack2(acc[i][j]);
            r[j] = p.x + p.y + ((n < NG_) ? bias[n] : 0.f);
        }
        float4 o; o.x = r[0]; o.y = r[1]; o.z = r[2]; o.w = r[3];
        *(float4*)&g_zx[dir][m][n0 + nt * 4] = o;   // pad cols written, never read
    }
}

// ------------------- kernel 2: persistent bidirectional LSTM ---------------
// 120 CTAs: dir(2) x batch-group(4 of 8) x unit-group(15 of 20 units).
// Wr slice pinned in registers as f32x2 col-pairs; h exchanged via L2 (+sense barrier).
__global__ void __launch_bounds__(RTHREADS, 1) lstm_recur(const float* __restrict__ WrF,
                                                          const float* __restrict__ WrB,
                                                          const int* __restrict__ seqlen) {
    const int bx  = blockIdx.x;          // 0..119
    const int dir = bx / 60;
    const int rem = bx % 60;
    const int bg  = rem / UGN;           // 0..3
    const int ug  = rem % UGN;           // 0..14
    const int grp = dir * 4 + bg;        // 0..7
    const float* __restrict__ Wr = dir ? WrB : WrF;
    const int u0  = ug * NU;
    const int tid = threadIdx.x;

    __shared__ ulonglong2 hh2[BG][150];          // h duplicated (v,v): 19200 B
    __shared__ float red_s[KCH][BG][NCOL];       // partial sums: 25600 B
    __shared__ float c_s[BG][NU], h_s[BG][NU];
    __shared__ int   seq_s[BG];

    const int  kch = tid / NCP;          // 0..9 valid
    const int  cp  = tid % NCP;          // 0..39
    const bool mm  = (tid < KCH * NCP);  // 400 matmul threads

    // ---- preload Wr slice into registers: w2[j] = (Wr[k][c0], Wr[k][c1]) ----
    unsigned long long w2[KC];
    if (mm) {
        int c0 = 2 * cp, c1 = 2 * cp + 1;
        int gc0 = (c0 / NU) * U_ + u0 + (c0 % NU);
        int gc1 = (c1 / NU) * U_ + u0 + (c1 % NU);
#pragma unroll
        for (int j = 0; j < KC; j++) {
            int k = kch * KC + j;
            w2[j] = pack2(Wr[(size_t)k * NG_ + gc0], Wr[(size_t)k * NG_ + gc1]);
        }
    }
    if (tid < BG) seq_s[tid] = seqlen[bg * BG + tid];
    for (int x = tid; x < BG * U_; x += RTHREADS)
        ((float2*)&hh2[x / U_][0])[x % U_] = make_float2(0.f, 0.f);
    if (tid < BG * NU) { c_s[tid / NU][tid % NU] = 0.f; h_s[tid / NU][tid % NU] = 0.f; }
    __syncthreads();

    unsigned ls = 0;
    volatile unsigned* cnt = &g_sync[grp][0];
    volatile unsigned* sns = &g_sync[grp][32];

    for (int s = 0; s < T_; s++) {
        const int t = dir ? (T_ - 1 - s) : s;

        // ---- matmul: z_partial[b][cols] over this thread's k-chunk ----
        if (mm) {
#pragma unroll
            for (int b = 0; b < BG; b++) {
                const ulonglong2* hp = &hh2[b][kch * (KC / 2)];
                unsigned long long acc = 0ULL;
#pragma unroll
                for (int jj = 0; jj < KC / 2; jj++) {
                    ulonglong2 h2 = hp[jj];
                    ffma2(acc, w2[2 * jj],     h2.x);
                    ffma2(acc, w2[2 * jj + 1], h2.y);
                }
                *(float2*)&red_s[kch][b][2 * cp] = unpack2(acc);
            }
        }
        __syncthreads();

        // ---- reduce + gates + state update (160 threads: b x unit) ----
        if (tid < BG * NU) {
            int b = tid / NU, i = tid % NU;
            int u  = u0 + i;
            int gb = bg * BG + b;
            const float* zrow = &g_zx[dir][gb * T_ + t][0];
            float z[4];
#pragma unroll
            for (int g = 0; g < 4; g++) {
                float sum = zrow[g * U_ + u];
#pragma unroll
                for (int kc2 = 0; kc2 < KCH; kc2++) sum += red_s[kc2][b][g * NU + i];
                z[g] = sum;
            }
            float ig = sigm(z[0]), fg = sigm(z[1]);
            float gg = tanhf(z[2]), og = sigm(z[3]);
            float c_old = c_s[b][i], h_old = h_s[b][i];
            float c_new = fg * c_old + ig * gg;
            float h_new = og * tanhf(c_new);
            bool  mk = (t < seq_s[b]);
            float hw = mk ? h_new : h_old;
            float cw = mk ? c_new : c_old;
            c_s[b][i] = cw;
            h_s[b][i] = hw;
            __stcg(&g_h[s & 1][dir][gb][u], hw);   // publish (L1 bypass)
            g_hs[dir][gb][t][u] = hw;              // history for fc
        }
        __syncthreads();

        // ---- inter-CTA sense-reversing barrier (15 CTAs of this group) ----
        if (tid == 0) {
            __threadfence();                       // release h stores
            ls ^= 1;
            unsigned old = atomicAdd((unsigned*)cnt, 1);
            if (old == UGN - 1) {
                *cnt = 0;
                __threadfence();
                *sns = ls;
            } else {
                while (*sns != ls) { }
            }
            __threadfence();                       // acquire
        }
        __syncthreads();

        // ---- reload full h for next step (L1 bypass, duplicated pairs) ----
        {
            const float* hsrc = &g_h[s & 1][dir][bg * BG][0];
            for (int x = tid; x < BG * U_; x += RTHREADS) {
                float v = __ldcg(hsrc + x);
                ((float2*)&hh2[x / U_][0])[x % U_] = make_float2(v, v);
            }
        }
        __syncthreads();
    }
}

// ------------------- kernel 3: out = [h_fwd|h_bwd] @ fc_W + fc_b -----------
__global__ void __launch_bounds__(256) fc_kernel(const float* __restrict__ fcW,
                                                 const float* __restrict__ fcb,
                                                 float* __restrict__ out) {
    __shared__ float Ws[1803];
    const int tid = threadIdx.x;
    for (int x = tid; x < 1800; x += 256) Ws[x] = fcW[x];
    if (tid < 3) Ws[1800 + tid] = fcb[tid];
    __syncthreads();

    const int wid = tid >> 5, lane = tid & 31;
    const int r = blockIdx.x * 8 + wid;       // 0..16383
    const int b = r >> 9, t = r & 511;
    float a0 = 0.f, a1 = 0.f, a2 = 0.f;
    const float* hf = &g_hs[0][b][t][0];
    const float* hb = &g_hs[1][b][t][0];
    for (int k = lane; k < U_; k += 32) {
        float v = hf[k];
        a0 += v * Ws[k * 3];  a1 += v * Ws[k * 3 + 1];  a2 += v * Ws[k * 3 + 2];
        float w = hb[k];
        a0 += w * Ws[(U_ + k) * 3];  a1 += w * Ws[(U_ + k) * 3 + 1];  a2 += w * Ws[(U_ + k) * 3 + 2];
    }
#pragma unroll
    for (int off = 16; off; off >>= 1) {
        a0 += __shfl_down_sync(0xffffffffu, a0, off);
        a1 += __shfl_down_sync(0xffffffffu, a1, off);
        a2 += __shfl_down_sync(0xffffffffu, a2, off);
    }
    if (lane == 0) {
        out[r * 3 + 0] = a0 + Ws[1800];
        out[r * 3 + 1] = a1 + Ws[1801];
        out[r * 3 + 2] = a2 + Ws[1802];
    }
}

// ------------------- launch ------------------------------------------------
extern "C" void kernel_launch(void* const* d_in, const int* in_sizes, int n_in,
                              void* d_out, int out_size) {
    const int*   inputs = (const int*)d_in[0];
    const int*   seqlen = (const int*)d_in[1];
    const float* emb    = (const float*)d_in[2];
    const float* Wk_f   = (const float*)d_in[3];
    const float* Wr_f   = (const float*)d_in[4];
    const float* b_f    = (const float*)d_in[5];
    const float* Wk_b   = (const float*)d_in[6];
    const float* Wr_b   = (const float*)d_in[7];
    const float* b_b    = (const float*)d_in[8];
    const float* fc_W   = (const float*)d_in[9];
    const float* fc_b   = (const float*)d_in[10];
    float* out = (float*)d_out;

    gemm_zx<<<dim3(256, 19, 2), 256>>>(inputs, emb, Wk_f, Wk_b, b_f, b_b);
    lstm_recur<<<120, RTHREADS>>>(Wr_f, Wr_b, seqlen);
    fc_kernel<<<2048, 256>>>(fc_W, fc_b, out);
}

// round 7
// speedup vs baseline: 1.2414x; 1.2414x over previous
#include <cuda_runtime.h>
#include <cuda_bf16.h>
#include <cstdint>
#include <math.h>

#define B_    32
#define T_    512
#define D_    300
#define U_    300
#define NG_   1200       // 4*U
#define ZPAD  1216       // padded zx row stride
#define M_    16384      // B*T

// recurrence tiling
#define NU    20         // units per CTA (15 CTAs * 20 = 300 exact)
#define NCOL  80         // 4*NU gate columns per CTA
#define NCP   40         // column pairs
#define KCH   10         // k chunks
#define KC    30         // k per chunk (10*30 = 300)
#define BG    8          // batches per CTA (4 groups * 8 = 32)
#define UGN   15         // unit-group CTAs per (dir,batch-group)
#define RTHREADS 416

typedef unsigned long long ULL;

// ------------------- static device scratch (no allocs allowed) -------------
__device__ __align__(16) float g_zx[2][M_][ZPAD];     // x@Wk+b per dir
__device__ __align__(16) float g_hs[2][B_][T_][U_];   // h history per dir
__device__ __align__(16) float g_h[2][2][B_][U_];     // [parity][dir][b][u]
__device__ unsigned g_sync[8][64];                    // [grp]: [0]=cnt [32]=sense

// ------------------- helpers ----------------------------------------------
union UF2 { float2 f; ULL u; };
__device__ __forceinline__ ULL pack2(float a, float b) {
    UF2 x; x.f = make_float2(a, b); return x.u;
}
__device__ __forceinline__ float2 unpack2(ULL v) {
    UF2 x; x.u = v; return x.f;
}
__device__ __forceinline__ void ffma2(ULL& d, ULL a, ULL b) {
    asm("fma.rn.f32x2 %0, %1, %2, %0;" : "+l"(d) : "l"(a), "l"(b));
}
__device__ __forceinline__ float sigm(float x) { return 1.f / (1.f + __expf(-x)); }

// ------------------- kernel 1: zx = gather(emb) @ Wk + b -------------------
// M=16384, N=1200, K=300(pad 304). BM=128, BN=64, BK=16 (8 k-pairs), 256 thr.
// Micro 8(m)x4(n), indices strided by 16; k-paired fma.rn.f32x2.
// Smem ULL rows padded to 9 (18 banks) -> conflict-free micro loads.
// Double-buffered stages; 2 CTAs/SM.
#define GKT 19   // ceil(304/16)

__global__ void __launch_bounds__(256, 2) gemm_zx(const int* __restrict__ idx,
                                                  const float* __restrict__ WkF,
                                                  const float* __restrict__ WkB,
                                                  const float* __restrict__ bF,
                                                  const float* __restrict__ bB,
                                                  const float* __restrict__ emb) {
    const int dir = blockIdx.z;
    const float* __restrict__ Wk   = dir ? WkB : WkF;
    const float* __restrict__ bias = dir ? bB  : bF;
    const int m0 = blockIdx.x * 128;
    const int n0 = blockIdx.y * 64;
    const int tid = threadIdx.x;

    __shared__ ULL A_s[2][128][9];   // [stage][m][kp], pad 9
    __shared__ ULL B_s[2][64][9];    // [stage][n][kp], pad 9
    __shared__ int row_s[128];

    if (tid < 128) row_s[tid] = idx[m0 + tid];
    __syncthreads();

    const int mt = tid >> 4;   // 0..15
    const int nt = tid & 15;   // 0..15

    ULL acc[8][4];
#pragma unroll
    for (int i = 0; i < 8; i++)
#pragma unroll
        for (int j = 0; j < 4; j++) acc[i][j] = 0ULL;

    ULL aReg[4];
    ULL bReg[2];

    // ---- load stage for kt into regs ----
    auto grab = [&](int kt) {
#pragma unroll
        for (int l = 0; l < 4; l++) {
            int id = tid + 256 * l;           // 0..1023
            int m  = id >> 3;                 // 0..127
            int kp = id & 7;
            int k0 = kt * 16 + kp * 2;
            if (k0 < D_) {
                const float* ep = emb + (size_t)row_s[m] * D_ + k0;
                float2 v = *(const float2*)ep;          // D_=300 even: both valid
                aReg[l] = pack2(v.x, v.y);
            } else aReg[l] = 0ULL;
        }
#pragma unroll
        for (int l = 0; l < 2; l++) {
            int id = tid + 256 * l;           // 0..511
            int n  = id & 63;
            int kp = id >> 6;                 // 0..7
            int k0 = kt * 16 + kp * 2;
            int gn = n0 + n;
            if (k0 < D_ && gn < NG_) {
                float v0 = Wk[(size_t)k0 * NG_ + gn];
                float v1 = Wk[(size_t)(k0 + 1) * NG_ + gn];
                bReg[l] = pack2(v0, v1);
            } else bReg[l] = 0ULL;
        }
    };
    auto commit = [&](int st) {
#pragma unroll
        for (int l = 0; l < 4; l++) {
            int id = tid + 256 * l;
            A_s[st][id >> 3][id & 7] = aReg[l];
        }
#pragma unroll
        for (int l = 0; l < 2; l++) {
            int id = tid + 256 * l;
            B_s[st][id & 63][id >> 6] = bReg[l];
        }
    };

    grab(0); commit(0);
    __syncthreads();

    for (int kt = 0; kt < GKT; kt++) {
        const int st = kt & 1;
        if (kt + 1 < GKT) grab(kt + 1);

#pragma unroll
        for (int kp = 0; kp < 8; kp++) {
            ULL a2[8], b2[4];
#pragma unroll
            for (int i = 0; i < 8; i++) a2[i] = A_s[st][mt + 16 * i][kp];
#pragma unroll
            for (int j = 0; j < 4; j++) b2[j] = B_s[st][nt + 16 * j][kp];
#pragma unroll
            for (int i = 0; i < 8; i++)
#pragma unroll
                for (int j = 0; j < 4; j++) ffma2(acc[i][j], a2[i], b2[j]);
        }

        if (kt + 1 < GKT) commit((kt + 1) & 1);
        __syncthreads();
    }

    // ---- epilogue: reduce pair halves, add bias, store ----
#pragma unroll
    for (int i = 0; i < 8; i++) {
        int m = m0 + mt + 16 * i;
        float* orow = &g_zx[dir][m][0];
#pragma unroll
        for (int j = 0; j < 4; j++) {
            int n = n0 + nt + 16 * j;
            if (n < NG_) {
                float2 p = unpack2(acc[i][j]);
                orow[n] = p.x + p.y + bias[n];
            }
        }
    }
}

// ------------------- kernel 2: persistent bidirectional LSTM ---------------
// 120 CTAs: dir(2) x batch-group(4 of 8) x unit-group(15 of 20 units).
// Wr slice pinned in registers as f32x2 col-pairs; h exchanged via L2 (+sense barrier).
__global__ void __launch_bounds__(RTHREADS, 1) lstm_recur(const float* __restrict__ WrF,
                                                          const float* __restrict__ WrB,
                                                          const int* __restrict__ seqlen) {
    const int bx  = blockIdx.x;          // 0..119
    const int dir = bx / 60;
    const int rem = bx % 60;
    const int bg  = rem / UGN;           // 0..3
    const int ug  = rem % UGN;           // 0..14
    const int grp = dir * 4 + bg;        // 0..7
    const float* __restrict__ Wr = dir ? WrB : WrF;
    const int u0  = ug * NU;
    const int tid = threadIdx.x;

    __shared__ ulonglong2 hh2[BG][150];          // h duplicated (v,v): 19200 B
    __shared__ float red_s[KCH][BG][NCOL];       // partial sums: 25600 B
    __shared__ float c_s[BG][NU], h_s[BG][NU];
    __shared__ int   seq_s[BG];

    const int  kch = tid / NCP;          // 0..9 valid
    const int  cp  = tid % NCP;          // 0..39
    const bool mm  = (tid < KCH * NCP);  // 400 matmul threads

    // gate-thread mapping (tid < 160): b x unit
    const bool gt = (tid < BG * NU);
    const int  gb_ = tid / NU, gi_ = tid % NU;

    // ---- preload Wr slice into registers: w2[j] = (Wr[k][c0], Wr[k][c1]) ----
    ULL w2[KC];
    if (mm) {
        int c0 = 2 * cp, c1 = 2 * cp + 1;
        int gc0 = (c0 / NU) * U_ + u0 + (c0 % NU);
        int gc1 = (c1 / NU) * U_ + u0 + (c1 % NU);
#pragma unroll
        for (int j = 0; j < KC; j++) {
            int k = kch * KC + j;
            w2[j] = pack2(Wr[(size_t)k * NG_ + gc0], Wr[(size_t)k * NG_ + gc1]);
        }
    }
    if (tid < BG) seq_s[tid] = seqlen[bg * BG + tid];
    for (int x = tid; x < BG * U_; x += RTHREADS)
        ((float2*)&hh2[x / U_][0])[x % U_] = make_float2(0.f, 0.f);
    if (gt) { c_s[gb_][gi_] = 0.f; h_s[gb_][gi_] = 0.f; }
    __syncthreads();

    unsigned ls = 0;
    volatile unsigned* cnt = &g_sync[grp][0];
    volatile unsigned* sns = &g_sync[grp][32];

    for (int s = 0; s < T_; s++) {
        const int t = dir ? (T_ - 1 - s) : s;

        // ---- prefetch zx row for THIS step (latency hidden by matmul) ----
        float zpre[4];
        if (gt) {
            const float* zrow = &g_zx[dir][(bg * BG + gb_) * T_ + t][0];
            int u = u0 + gi_;
#pragma unroll
            for (int g = 0; g < 4; g++) zpre[g] = __ldcg(zrow + g * U_ + u);
        }

        // ---- matmul: z_partial[b][cols] over this thread's k-chunk ----
        if (mm) {
#pragma unroll
            for (int b = 0; b < BG; b++) {
                const ulonglong2* hp = &hh2[b][kch * (KC / 2)];
                ULL acc = 0ULL;
#pragma unroll
                for (int jj = 0; jj < KC / 2; jj++) {
                    ulonglong2 h2 = hp[jj];
                    ffma2(acc, w2[2 * jj],     h2.x);
                    ffma2(acc, w2[2 * jj + 1], h2.y);
                }
                *(float2*)&red_s[kch][b][2 * cp] = unpack2(acc);
            }
        }
        __syncthreads();

        // ---- reduce + gates + state update (160 threads: b x unit) ----
        if (gt) {
            int b = gb_, i = gi_;
            int u  = u0 + i;
            int gb = bg * BG + b;
            float z[4];
#pragma unroll
            for (int g = 0; g < 4; g++) {
                float sum = zpre[g];
#pragma unroll
                for (int kc2 = 0; kc2 < KCH; kc2++) sum += red_s[kc2][b][g * NU + i];
                z[g] = sum;
            }
            float ig = sigm(z[0]), fg = sigm(z[1]);
            float gg = tanhf(z[2]), og = sigm(z[3]);
            float c_old = c_s[b][i], h_old = h_s[b][i];
            float c_new = fg * c_old + ig * gg;
            float h_new = og * tanhf(c_new);
            bool  mk = (t < seq_s[b]);
            float hw = mk ? h_new : h_old;
            float cw = mk ? c_new : c_old;
            c_s[b][i] = cw;
            h_s[b][i] = hw;
            __stcg(&g_h[s & 1][dir][gb][u], hw);   // publish (L1 bypass)
            g_hs[dir][gb][t][u] = hw;              // history for fc
        }
        __syncthreads();

        // ---- inter-CTA sense-reversing barrier (15 CTAs of this group) ----
        if (tid == 0) {
            __threadfence();                       // release h stores
            ls ^= 1;
            unsigned old = atomicAdd((unsigned*)cnt, 1);
            if (old == UGN - 1) {
                *cnt = 0;
                __threadfence();
                *sns = ls;
            } else {
                while (*sns != ls) { }
            }
            __threadfence();                       // acquire
        }
        __syncthreads();

        // ---- reload full h for next step (L1 bypass, duplicated pairs) ----
        {
            const float* hsrc = &g_h[s & 1][dir][bg * BG][0];
            for (int x = tid; x < BG * U_; x += RTHREADS) {
                float v = __ldcg(hsrc + x);
                ((float2*)&hh2[x / U_][0])[x % U_] = make_float2(v, v);
            }
        }
        __syncthreads();
    }
}

// ------------------- kernel 3: out = [h_fwd|h_bwd] @ fc_W + fc_b -----------
__global__ void __launch_bounds__(256) fc_kernel(const float* __restrict__ fcW,
                                                 const float* __restrict__ fcb,
                                                 float* __restrict__ out) {
    __shared__ float Ws[1803];
    const int tid = threadIdx.x;
    for (int x = tid; x < 1800; x += 256) Ws[x] = fcW[x];
    if (tid < 3) Ws[1800 + tid] = fcb[tid];
    __syncthreads();

    const int wid = tid >> 5, lane = tid & 31;
    const int r = blockIdx.x * 8 + wid;       // 0..16383
    const int b = r >> 9, t = r & 511;
    float a0 = 0.f, a1 = 0.f, a2 = 0.f;
    const float* hf = &g_hs[0][b][t][0];
    const float* hb = &g_hs[1][b][t][0];
    for (int k = lane; k < U_; k += 32) {
        float v = hf[k];
        a0 += v * Ws[k * 3];  a1 += v * Ws[k * 3 + 1];  a2 += v * Ws[k * 3 + 2];
        float w = hb[k];
        a0 += w * Ws[(U_ + k) * 3];  a1 += w * Ws[(U_ + k) * 3 + 1];  a2 += w * Ws[(U_ + k) * 3 + 2];
    }
#pragma unroll
    for (int off = 16; off; off >>= 1) {
        a0 += __shfl_down_sync(0xffffffffu, a0, off);
        a1 += __shfl_down_sync(0xffffffffu, a1, off);
        a2 += __shfl_down_sync(0xffffffffu, a2, off);
    }
    if (lane == 0) {
        out[r * 3 + 0] = a0 + Ws[1800];
        out[r * 3 + 1] = a1 + Ws[1801];
        out[r * 3 + 2] = a2 + Ws[1802];
    }
}

// ------------------- launch ------------------------------------------------
extern "C" void kernel_launch(void* const* d_in, const int* in_sizes, int n_in,
                              void* d_out, int out_size) {
    const int*   inputs = (const int*)d_in[0];
    const int*   seqlen = (const int*)d_in[1];
    const float* emb    = (const float*)d_in[2];
    const float* Wk_f   = (const float*)d_in[3];
    const float* Wr_f   = (const float*)d_in[4];
    const float* b_f    = (const float*)d_in[5];
    const float* Wk_b   = (const float*)d_in[6];
    const float* Wr_b   = (const float*)d_in[7];
    const float* b_b    = (const float*)d_in[8];
    const float* fc_W   = (const float*)d_in[9];
    const float* fc_b   = (const float*)d_in[10];
    float* out = (float*)d_out;

    gemm_zx<<<dim3(128, 19, 2), 256>>>(inputs, Wk_f, Wk_b, b_f, b_b, emb);
    lstm_recur<<<120, RTHREADS>>>(Wr_f, Wr_b, seqlen);
    fc_kernel<<<2048, 256>>>(fc_W, fc_b, out);
}